// round 9
// baseline (speedup 1.0000x reference)
#include <cuda_runtime.h>
#include <mma.h>
#include <cstdint>
#include <cstddef>

using namespace nvcuda;

#define V_N 4000
#define E_N 40000
#define E_PAD 40064          // 313 * 128
#define D_F 64
#define G_N 40
#define NPG 100              // nodes per graph (graph_ids = floor(v/100) by construction)
#define NODE_IN 74
#define EHID 128
#define NCOL 4096            // D*D
#define NSTEPS 6
#define S2S_ITERS 6

// ---------------- static device scratch (no allocations allowed) ----------------
// NOTE: these are referenced ONLY from device code (never passed as host-side args).
__device__ float g_h[V_N * D_F];              // node hidden state
__device__ float g_agg[V_N * D_F];            // NNConv aggregation buffer
__device__ float g_mid[(size_t)E_PAD * EHID]; // relu(ef @ W_e1 + b_e1)
__device__ float g_ew[(size_t)E_PAD * NCOL];  // edge weight matrices (E,64,64) ~656MB

__device__ __forceinline__ float sigf(float x) { return 1.0f / (1.0f + expf(-x)); }

// round-to-nearest tf32 value, returned in a float container
__device__ __forceinline__ float tf32r(float x) {
    uint32_t u;
    asm("cvt.rna.tf32.f32 %0, %1;" : "=r"(u) : "f"(x));
    return __uint_as_float(u);
}

// ---------------- 1. node projection: h = relu(nf @ W_proj + b), also zero agg ----------------
__global__ __launch_bounds__(256) void proj_kernel(
    const float* __restrict__ nf, const float* __restrict__ W, const float* __restrict__ b)
{
    int local = threadIdx.x >> 6;
    int j = threadIdx.x & 63;
    int v = blockIdx.x * 4 + local;
    __shared__ float s[4][NODE_IN];
    for (int k = j; k < NODE_IN; k += 64) s[local][k] = nf[v * NODE_IN + k];
    __syncthreads();
    float acc = b[j];
    #pragma unroll 2
    for (int k = 0; k < NODE_IN; k++) acc = fmaf(s[local][k], W[k * D_F + j], acc);
    g_h[v * D_F + j] = fmaxf(acc, 0.0f);
    g_agg[v * D_F + j] = 0.0f;
}

// ---------------- 2+3. wmma tf32x3 GEMM ----------------
// PHASE 0: g_mid = relu(edge_feats[E x 128] @ W_e1[128 x 128] + b_e1), rows >= E_N zero-padded
// PHASE 1: g_ew  = g_mid[E_PAD x 128] @ W_e2[128 x 4096] + b_e2
// block tile 128x128, K chunk 16, 256 threads = 8 warps (2M x 4N), warp tile 64x32.
// A,B split into tf32 hi/lo at staging; acc += Ah*Bh + Al*Bh + Ah*Bl  (fp32-grade accuracy).
#define APAD 20
#define BPAD 136

template<int PHASE>
__global__ __launch_bounds__(256) void gemm_wmma(
    const float* __restrict__ Aext,     // used only in PHASE 0 (edge_feats)
    const float* __restrict__ Bm,       // weight matrix [128 x N], row-major
    const float* __restrict__ bias)     // [N]
{
    constexpr bool RELU  = (PHASE == 0);
    constexpr bool GUARD = (PHASE == 0);
    constexpr int  N     = (PHASE == 0) ? EHID : NCOL;
    const float* A = (PHASE == 0) ? Aext : g_mid;   // device globals bound in device code
    float*       C = (PHASE == 0) ? g_mid : g_ew;

    __shared__ float Ah[128][APAD], Al[128][APAD];   // [m][k-chunk]
    __shared__ float Bh[16][BPAD],  Bl[16][BPAD];    // [k-chunk][n]
    __shared__ float patch[8][16 * 20];              // per-warp epilogue staging

    int tid  = threadIdx.x;
    int warp = tid >> 5;
    int lane = tid & 31;
    int warpM = (warp & 1) * 64;
    int warpN = (warp >> 1) * 32;
    int bm = blockIdx.x, bn = blockIdx.y;

    wmma::fragment<wmma::accumulator, 16, 16, 8, float> acc[4][2];
    #pragma unroll
    for (int mf = 0; mf < 4; mf++)
        #pragma unroll
        for (int nf = 0; nf < 2; nf++) wmma::fill_fragment(acc[mf][nf], 0.0f);

    int aRow = tid >> 1;            // 0..127
    int aCol = (tid & 1) * 8;       // 0 or 8
    int bRow = tid >> 4;            // 0..15
    int bCol = (tid & 15) * 8;      // 0..120

    for (int k0 = 0; k0 < 128; k0 += 16) {
        // global loads into registers (overlap tail of previous chunk's compute)
        float4 a0, a1, b0, b1;
        int grow = bm * 128 + aRow;
        if (!GUARD || grow < E_N) {
            a0 = *reinterpret_cast<const float4*>(A + (size_t)grow * 128 + k0 + aCol);
            a1 = *reinterpret_cast<const float4*>(A + (size_t)grow * 128 + k0 + aCol + 4);
        } else {
            a0 = make_float4(0.f, 0.f, 0.f, 0.f);
            a1 = a0;
        }
        b0 = *reinterpret_cast<const float4*>(Bm + (size_t)(k0 + bRow) * N + bn * 128 + bCol);
        b1 = *reinterpret_cast<const float4*>(Bm + (size_t)(k0 + bRow) * N + bn * 128 + bCol + 4);

        __syncthreads();   // previous chunk fully consumed
        {
            float av[8] = {a0.x, a0.y, a0.z, a0.w, a1.x, a1.y, a1.z, a1.w};
            float bv[8] = {b0.x, b0.y, b0.z, b0.w, b1.x, b1.y, b1.z, b1.w};
            #pragma unroll
            for (int i = 0; i < 8; i++) {
                float hi = tf32r(av[i]);
                Ah[aRow][aCol + i] = hi;
                Al[aRow][aCol + i] = tf32r(av[i] - hi);
                float hib = tf32r(bv[i]);
                Bh[bRow][bCol + i] = hib;
                Bl[bRow][bCol + i] = tf32r(bv[i] - hib);
            }
        }
        __syncthreads();

        #pragma unroll
        for (int ks = 0; ks < 2; ks++) {
            int kk = ks * 8;
            wmma::fragment<wmma::matrix_b, 16, 16, 8, wmma::precision::tf32, wmma::row_major> fbh[2], fbl[2];
            #pragma unroll
            for (int nf = 0; nf < 2; nf++) {
                wmma::load_matrix_sync(fbh[nf], &Bh[kk][warpN + nf * 16], BPAD);
                wmma::load_matrix_sync(fbl[nf], &Bl[kk][warpN + nf * 16], BPAD);
            }
            #pragma unroll
            for (int mf = 0; mf < 4; mf++) {
                wmma::fragment<wmma::matrix_a, 16, 16, 8, wmma::precision::tf32, wmma::row_major> fah, fal;
                wmma::load_matrix_sync(fah, &Ah[warpM + mf * 16][kk], APAD);
                wmma::load_matrix_sync(fal, &Al[warpM + mf * 16][kk], APAD);
                #pragma unroll
                for (int nf = 0; nf < 2; nf++) {
                    wmma::mma_sync(acc[mf][nf], fah, fbh[nf], acc[mf][nf]);
                    wmma::mma_sync(acc[mf][nf], fal, fbh[nf], acc[mf][nf]);
                    wmma::mma_sync(acc[mf][nf], fah, fbl[nf], acc[mf][nf]);
                }
            }
        }
    }

    // epilogue: per-warp smem round-trip -> explicit (row,col), + bias, optional relu
    int r  = lane >> 1;
    int c8 = (lane & 1) * 8;
    #pragma unroll
    for (int nf = 0; nf < 2; nf++) {
        int colg = bn * 128 + warpN + nf * 16 + c8;
        float4 bv0 = *reinterpret_cast<const float4*>(bias + colg);
        float4 bv1 = *reinterpret_cast<const float4*>(bias + colg + 4);
        #pragma unroll
        for (int mf = 0; mf < 4; mf++) {
            wmma::store_matrix_sync(&patch[warp][0], acc[mf][nf], 20, wmma::mem_row_major);
            __syncwarp();
            float v[8];
            #pragma unroll
            for (int i = 0; i < 8; i++) v[i] = patch[warp][r * 20 + c8 + i];
            v[0] += bv0.x; v[1] += bv0.y; v[2] += bv0.z; v[3] += bv0.w;
            v[4] += bv1.x; v[5] += bv1.y; v[6] += bv1.z; v[7] += bv1.w;
            if (RELU) {
                #pragma unroll
                for (int i = 0; i < 8; i++) v[i] = fmaxf(v[i], 0.0f);
            }
            int rowg = bm * 128 + warpM + mf * 16 + r;
            float* cp = C + (size_t)rowg * N + colg;
            *reinterpret_cast<float4*>(cp)     = make_float4(v[0], v[1], v[2], v[3]);
            *reinterpret_cast<float4*>(cp + 4) = make_float4(v[4], v[5], v[6], v[7]);
            __syncwarp();
        }
    }
}

// ---------------- 4. per-step messages: msg[e] = h[src[e]] @ ew[e]; scatter-add to agg[dst] ----------------
__global__ __launch_bounds__(256) void msg_kernel(
    const int* __restrict__ src, const int* __restrict__ dst)
{
    int local = threadIdx.x >> 6;
    int o = threadIdx.x & 63;
    int e = blockIdx.x * 4 + local;
    __shared__ float sh[4][D_F];
    sh[local][o] = g_h[src[e] * D_F + o];
    __syncthreads();
    const float* w = g_ew + (size_t)e * NCOL + o;
    float acc = 0.0f;
    #pragma unroll
    for (int i = 0; i < D_F; i++) acc = fmaf(sh[local][i], w[i * D_F], acc);
    atomicAdd(&g_agg[dst[e] * D_F + o], acc);
}

// ---------------- 5. GRU: hidden = GRU(relu(agg + b_conv), hidden); re-zero agg ----------------
// (exact copy of the round-4 passing version)
__global__ __launch_bounds__(256) void gru_kernel(
    const float* __restrict__ bconv,
    const float* __restrict__ Wih, const float* __restrict__ Whh,
    const float* __restrict__ bih, const float* __restrict__ bhh)
{
    int local = threadIdx.x >> 6;
    int j = threadIdx.x & 63;
    int v = blockIdx.x * 4 + local;
    __shared__ float sx[4][D_F], sh[4][D_F];
    sx[local][j] = fmaxf(g_agg[v * D_F + j] + bconv[j], 0.0f);
    sh[local][j] = g_h[v * D_F + j];
    g_agg[v * D_F + j] = 0.0f;   // ready for next step
    __syncthreads();
    float gir = bih[j], giz = bih[64 + j], gin = bih[128 + j];
    float ghr = bhh[j], ghz = bhh[64 + j], ghn = bhh[128 + j];
    for (int k = 0; k < D_F; k++) {
        float xv = sx[local][k], hv = sh[local][k];
        gir = fmaf(xv, Wih[j * D_F + k], gir);
        giz = fmaf(xv, Wih[(64 + j) * D_F + k], giz);
        gin = fmaf(xv, Wih[(128 + j) * D_F + k], gin);
        ghr = fmaf(hv, Whh[j * D_F + k], ghr);
        ghz = fmaf(hv, Whh[(64 + j) * D_F + k], ghz);
        ghn = fmaf(hv, Whh[(128 + j) * D_F + k], ghn);
    }
    float r = sigf(gir + ghr);
    float z = sigf(giz + ghz);
    float n = tanhf(gin + r * ghn);
    g_h[v * D_F + j] = (1.0f - z) * n + z * sh[local][j];
}

// ---------------- 6. Set2Set + predict, one block per graph ----------------
__device__ __forceinline__ void lstm_layer(
    int tid, const float* __restrict__ x, int in_dim,
    float* hvec, float* cvec,
    const float* __restrict__ Wih, const float* __restrict__ Whh,
    const float* __restrict__ bih, const float* __restrict__ bhh,
    float* gates)
{
    #pragma unroll
    for (int rep = 0; rep < 2; rep++) {
        int j = tid + rep * 128;
        float acc = bih[j] + bhh[j];
        for (int k = 0; k < in_dim; k++) acc = fmaf(x[k], Wih[j * in_dim + k], acc);
        for (int k = 0; k < D_F; k++)   acc = fmaf(hvec[k], Whh[j * D_F + k], acc);
        gates[j] = acc;
    }
    __syncthreads();
    if (tid < 64) {
        float i_ = sigf(gates[tid]);
        float f_ = sigf(gates[64 + tid]);
        float g_ = tanhf(gates[128 + tid]);
        float o_ = sigf(gates[192 + tid]);
        float c = f_ * cvec[tid] + i_ * g_;
        cvec[tid] = c;
        hvec[tid] = o_ * tanhf(c);
    }
    __syncthreads();
}

__global__ __launch_bounds__(128) void s2s_kernel(
    const float* __restrict__ Wih0, const float* __restrict__ Whh0,
    const float* __restrict__ bih0, const float* __restrict__ bhh0,
    const float* __restrict__ Wih1, const float* __restrict__ Whh1,
    const float* __restrict__ bih1, const float* __restrict__ bhh1,
    const float* __restrict__ Wih2, const float* __restrict__ Whh2,
    const float* __restrict__ bih2, const float* __restrict__ bhh2,
    const float* __restrict__ Wp1, const float* __restrict__ bp1,
    const float* __restrict__ Wp2, const float* __restrict__ bp2,
    float* __restrict__ out)
{
    __shared__ float shh[NPG * 65];
    __shared__ float hs[3][D_F], cs[3][D_F], qstar[2 * D_F], gates[256];
    __shared__ float ebuf[NPG], pbuf[D_F];
    __shared__ float mred, sred;
    int g = blockIdx.x, tid = threadIdx.x;

    const float* hg = g_h + (size_t)g * NPG * D_F;
    for (int idx = tid; idx < NPG * D_F; idx += 128) {
        int n = idx >> 6, k = idx & 63;
        shh[n * 65 + k] = hg[idx];
    }
    if (tid < 64) {
        #pragma unroll
        for (int l = 0; l < 3; l++) { hs[l][tid] = 0.0f; cs[l][tid] = 0.0f; }
        qstar[tid] = 0.0f; qstar[64 + tid] = 0.0f;
    }
    __syncthreads();

    for (int it = 0; it < S2S_ITERS; it++) {
        lstm_layer(tid, qstar, 2 * D_F, hs[0], cs[0], Wih0, Whh0, bih0, bhh0, gates);
        lstm_layer(tid, hs[0],  D_F,    hs[1], cs[1], Wih1, Whh1, bih1, bhh1, gates);
        lstm_layer(tid, hs[1],  D_F,    hs[2], cs[2], Wih2, Whh2, bih2, bhh2, gates);
        if (tid < NPG) {
            float a = 0.0f;
            for (int k = 0; k < D_F; k++) a = fmaf(shh[tid * 65 + k], hs[2][k], a);
            ebuf[tid] = a;
        }
        __syncthreads();
        if (tid == 0) {
            float m = -1e30f;
            for (int n = 0; n < NPG; n++) m = fmaxf(m, ebuf[n]);
            mred = m;
        }
        __syncthreads();
        if (tid < NPG) ebuf[tid] = expf(ebuf[tid] - mred);
        __syncthreads();
        if (tid == 0) {
            float s = 0.0f;
            for (int n = 0; n < NPG; n++) s += ebuf[n];
            sred = s;
        }
        __syncthreads();
        if (tid < 64) {
            float r = 0.0f;
            for (int n = 0; n < NPG; n++) r = fmaf(ebuf[n], shh[n * 65 + tid], r);
            qstar[64 + tid] = r / sred;
            qstar[tid] = hs[2][tid];
        }
        __syncthreads();
    }

    if (tid < 64) {
        float acc = bp1[tid];
        for (int k = 0; k < 2 * D_F; k++) acc = fmaf(qstar[k], Wp1[k * D_F + tid], acc);
        pbuf[tid] = fmaxf(acc, 0.0f);
    }
    __syncthreads();
    if (tid == 0) {
        float acc = bp2[0];
        for (int d = 0; d < D_F; d++) acc = fmaf(pbuf[d], Wp2[d], acc);
        out[g] = acc;
    }
}

// ---------------- launcher ----------------
extern "C" void kernel_launch(void* const* d_in, const int* in_sizes, int n_in,
                              void* d_out, int out_size)
{
    const float* node_feats = (const float*)d_in[0];
    const float* edge_feats = (const float*)d_in[1];
    const int*   src        = (const int*)d_in[2];
    const int*   dst        = (const int*)d_in[3];
    // d_in[4] graph_ids: unused (graphs are contiguous 100-node blocks by construction)
    const float* W_proj = (const float*)d_in[5];
    const float* b_proj = (const float*)d_in[6];
    const float* W_e1   = (const float*)d_in[7];
    const float* b_e1   = (const float*)d_in[8];
    const float* W_e2   = (const float*)d_in[9];
    const float* b_e2   = (const float*)d_in[10];
    const float* b_conv = (const float*)d_in[11];
    const float* W_ih   = (const float*)d_in[12];
    const float* W_hh   = (const float*)d_in[13];
    const float* b_ih   = (const float*)d_in[14];
    const float* b_hh   = (const float*)d_in[15];
    const float* Wih0 = (const float*)d_in[16]; const float* Whh0 = (const float*)d_in[17];
    const float* bih0 = (const float*)d_in[18]; const float* bhh0 = (const float*)d_in[19];
    const float* Wih1 = (const float*)d_in[20]; const float* Whh1 = (const float*)d_in[21];
    const float* bih1 = (const float*)d_in[22]; const float* bhh1 = (const float*)d_in[23];
    const float* Wih2 = (const float*)d_in[24]; const float* Whh2 = (const float*)d_in[25];
    const float* bih2 = (const float*)d_in[26]; const float* bhh2 = (const float*)d_in[27];
    const float* W_p1 = (const float*)d_in[28]; const float* b_p1 = (const float*)d_in[29];
    const float* W_p2 = (const float*)d_in[30]; const float* b_p2 = (const float*)d_in[31];
    float* out = (float*)d_out;

    // phase A: projection + edge network (step-invariant), tf32x3 tensor cores.
    // Internal buffers (g_mid, g_ew) are bound inside device code via the PHASE template
    // — never passed as host-side arguments (that was the R5/R6 bug).
    proj_kernel<<<V_N / 4, 256>>>(node_feats, W_proj, b_proj);
    gemm_wmma<0><<<dim3(E_PAD / 128, 1), 256>>>(edge_feats, W_e1, b_e1);
    gemm_wmma<1><<<dim3(E_PAD / 128, NCOL / 128), 256>>>(nullptr, W_e2, b_e2);

    // phase B: 6 message-passing + GRU steps
    for (int s = 0; s < NSTEPS; s++) {
        msg_kernel<<<E_N / 4, 256>>>(src, dst);
        gru_kernel<<<V_N / 4, 256>>>(b_conv, W_ih, W_hh, b_ih, b_hh);
    }

    // phase C: set2set readout + predictor, one block per graph
    s2s_kernel<<<G_N, 128>>>(Wih0, Whh0, bih0, bhh0,
                             Wih1, Whh1, bih1, bhh1,
                             Wih2, Whh2, bih2, bhh2,
                             W_p1, b_p1, W_p2, b_p2, out);
}